// round 14
// baseline (speedup 1.0000x reference)
#include <cuda_runtime.h>
#include <stdint.h>

// Problem constants (fixed by the reference)
#define BATCH 4096
#define V     64
#define D     63
#define DEPTH 16
#define WPB   4            // warps (batch rows) per block
#define FULL  0xffffffffu

__device__ __forceinline__ unsigned float_to_ordered(float f) {
    unsigned u = __float_as_uint(f);
    return (u & 0x80000000u) ? ~u : (u | 0x80000000u);
}

__global__ __launch_bounds__(WPB * 32, 8)
void scn_kernel(const float* __restrict__ inp,
                const float* __restrict__ L,
                const float* __restrict__ visible_fs,
                const float* __restrict__ visible_units,
                const float* __restrict__ biases,
                float* __restrict__ out)
{
    __shared__ float vu_s[V][64];                 // visible_units, D padded to 64 (16 KB)
    __shared__ float Ls[DEPTH][V];                // L matrix (4 KB)
    __shared__ int   ovr_s[WPB][V];               // per-warp: depth of latest override, or -1 (1 KB)
    __shared__ float bias_s[DEPTH];
    // ~21.3 KB smem -> 8 blocks/SM (regs <= 64) -> 1184 resident >= 1024 = SINGLE WAVE

    // per-thread h_sel history (dynamic index -> local memory, L1-cached, warp-uniform reads)
    float hist0[DEPTH];
    float hist1[DEPTH];

    const int tid  = threadIdx.x;
    const int wid  = tid >> 5;
    const int lane = tid & 31;

    // ---- block-shared loads ----
    for (int k = tid; k < V * D; k += blockDim.x)
        vu_s[k / D][k % D] = visible_units[k];
    for (int k = tid; k < DEPTH * V; k += blockDim.x)
        Ls[k / V][k % V] = L[k];
    if (tid < DEPTH) bias_s[tid] = biases[tid];
    if (tid < V)     vu_s[tid][63] = 0.0f;        // pad column (never consumed as output)
    __syncthreads();

    const int b = blockIdx.x * WPB + wid;         // batch row for this warp

    const int v0 = lane;                           // this lane owns v = lane and v = 32+lane
    const int v1 = 32 + lane;

    // ---- init per-row state: w (barycentric weights), f ----
    const float* inp_row = inp + (size_t)b * D;
    float w0 = (v0 == 0) ? 0.0f : inp_row[v0 - 1];
    float w1 = inp_row[v1 - 1];                    // v1-1 in [31,62], valid

    {
        float s = __fadd_rn(w0, w1);
        #pragma unroll
        for (int o = 16; o; o >>= 1) s = __fadd_rn(s, __shfl_xor_sync(FULL, s, o));
        if (lane == 0) w0 = __fsub_rn(1.0f, s);
    }

    float f0 = visible_fs[v0];
    float f1 = visible_fs[v1];

    ovr_s[wid][v0] = -1;
    ovr_s[wid][v1] = -1;
    __syncwarp();

    // ---- output layout: [ out(B) | h_old_all(DEPTH,B,V,D) | h_sel_all(DEPTH,B,D) ] ----
    float* out_scalar = out;
    float* h_old      = out + BATCH;
    float* h_sel_out  = h_old + (size_t)DEPTH * BATCH * V * D;

    for (int i = 0; i < DEPTH; ++i) {
        const float li0 = Ls[i][v0];
        const float li1 = Ls[i][v1];
        const float r0 = __fdiv_rn(1.0f, __fadd_rn(li0, 1e-20f));
        const float r1 = __fdiv_rn(1.0f, __fadd_rn(li1, 1e-20f));

        // ---- argmin of wd = w * fl(1/(Li+1e-20))  [XLA recip-mul], first-index tie-break ----
        float wd0 = __fmul_rn(w0, r0);
        float wd1 = __fmul_rn(w1, r1);
        unsigned long long k0 = ((unsigned long long)float_to_ordered(wd0) << 32) | (unsigned)v0;
        unsigned long long k1 = ((unsigned long long)float_to_ordered(wd1) << 32) | (unsigned)v1;
        unsigned long long kk = k0 < k1 ? k0 : k1;
        #pragma unroll
        for (int o = 16; o; o >>= 1) {
            unsigned long long other = __shfl_xor_sync(FULL, kk, o);
            kk = other < kk ? other : kk;
        }
        const int idx = (int)(unsigned)kk;
        unsigned ub = (unsigned)(kk >> 32);
        ub = (ub & 0x80000000u) ? (ub & 0x7fffffffu) : ~ub;
        const float val = __uint_as_float(ub);

        // ---- f_sel = Li . f + bias[i] ----
        float fp = __fmaf_rn(li0, f0, __fmul_rn(li1, f1));
        #pragma unroll
        for (int o = 16; o; o >>= 1) fp = __fadd_rn(fp, __shfl_xor_sync(FULL, fp, o));
        const float f_sel = __fadd_rn(fp, bias_s[i]);

        // ---- w update: single-rounded FMA (measured-correct form) ----
        w0 = __fmaf_rn(-val, li0, w0);
        w1 = __fmaf_rn(-val, li1, w1);
        if (v0 == idx) w0 = val;
        if (v1 == idx) w1 = val;

        // ---- snapshot h_old (pre-update) + h_sel = Li . h in same pass (R9 structure) ----
        float acc0 = 0.0f, acc1 = 0.0f;
        float* dst = h_old + ((size_t)i * BATCH + b) * (V * D);
        #pragma unroll 8
        for (int v = 0; v < V; ++v) {
            const float liv = Ls[i][v];
            const int   j   = ovr_s[wid][v];
            float s0, s1;
            if (j >= 0) { s0 = hist0[j];      s1 = hist1[j]; }
            else        { s0 = vu_s[v][lane]; s1 = vu_s[v][32 + lane]; }
            acc0 = __fmaf_rn(liv, s0, acc0);
            acc1 = __fmaf_rn(liv, s1, acc1);
            __stcs(&dst[v * D + lane], s0);                     // d = lane (0..31)
            if (lane < 31) __stcs(&dst[v * D + 32 + lane], s1); // d = 32+lane (32..62)
        }

        // ---- emit h_sel_all[i][b][:] ----
        float* hso = h_sel_out + ((size_t)i * BATCH + b) * D;
        __stcs(&hso[lane], acc0);
        if (lane < 31) __stcs(&hso[32 + lane], acc1);

        // ---- state updates: h[idx] <- h_sel (as override), f[idx] <- f_sel ----
        hist0[i] = acc0;
        hist1[i] = acc1;     // lane31 slot carries confined pad, never emitted
        if (v0 == idx) f0 = f_sel;
        if (v1 == idx) f1 = f_sel;
        if (lane == (idx & 31)) ovr_s[wid][idx] = i;
        __syncwarp();
    }

    // ---- out[b] = w . f (exact f32 fma tree) ----
    float p = __fmaf_rn(w0, f0, __fmul_rn(w1, f1));
    #pragma unroll
    for (int o = 16; o; o >>= 1) p = __fadd_rn(p, __shfl_xor_sync(FULL, p, o));
    if (lane == 0) out_scalar[b] = p;
}

extern "C" void kernel_launch(void* const* d_in, const int* in_sizes, int n_in,
                              void* d_out, int out_size) {
    const float* inp         = (const float*)d_in[0];
    const float* L           = (const float*)d_in[1];
    const float* visible_fs  = (const float*)d_in[2];
    const float* vis_units   = (const float*)d_in[3];
    const float* biases      = (const float*)d_in[4];
    float* out = (float*)d_out;

    dim3 grid(BATCH / WPB);
    dim3 block(WPB * 32);
    scn_kernel<<<grid, block>>>(inp, L, visible_fs, vis_units, biases, out);
}

// round 15
// speedup vs baseline: 1.0092x; 1.0092x over previous
#include <cuda_runtime.h>
#include <stdint.h>

// Problem constants (fixed by the reference)
#define BATCH 4096
#define V     64
#define D     63
#define DEPTH 16
#define WPB   4            // warps (batch rows) per block
#define FULL  0xffffffffu

__device__ __forceinline__ unsigned float_to_ordered(float f) {
    unsigned u = __float_as_uint(f);
    return (u & 0x80000000u) ? ~u : (u | 0x80000000u);
}

__global__ __launch_bounds__(WPB * 32)
void scn_kernel(const float* __restrict__ inp,
                const float* __restrict__ L,
                const float* __restrict__ visible_fs,
                const float* __restrict__ visible_units,
                const float* __restrict__ biases,
                float* __restrict__ out)
{
    __shared__ float vu_s[V][64];                 // visible_units, D padded to 64 (16 KB)
    __shared__ float Ls[DEPTH][V];                // L matrix (4 KB)
    __shared__ float hsel_s[WPB][DEPTH][64];      // per-warp stored h_sel vectors (16 KB)
    __shared__ int   ovr_s[WPB][V];               // per-warp: depth of latest override, or -1 (1 KB)
    __shared__ float bias_s[DEPTH];
    // ~37.3 KB -> 6 blocks/SM

    const int tid  = threadIdx.x;
    const int wid  = tid >> 5;
    const int lane = tid & 31;

    // ---- block-shared loads ----
    for (int k = tid; k < V * D; k += blockDim.x)
        vu_s[k / D][k % D] = visible_units[k];
    for (int k = tid; k < DEPTH * V; k += blockDim.x)
        Ls[k / V][k % V] = L[k];
    if (tid < DEPTH) bias_s[tid] = biases[tid];
    if (tid < V)     vu_s[tid][63] = 0.0f;        // pad column (never consumed as output)
    __syncthreads();

    const int b = blockIdx.x * WPB + wid;         // batch row for this warp

    const int v0 = lane;                           // this lane owns v = lane and v = 32+lane
    const int v1 = 32 + lane;

    // ---- init per-row state: w (barycentric weights), f ----
    const float* inp_row = inp + (size_t)b * D;
    float w0 = (v0 == 0) ? 0.0f : inp_row[v0 - 1];
    float w1 = inp_row[v1 - 1];                    // v1-1 in [31,62], valid

    {
        float s = __fadd_rn(w0, w1);
        #pragma unroll
        for (int o = 16; o; o >>= 1) s = __fadd_rn(s, __shfl_xor_sync(FULL, s, o));
        if (lane == 0) w0 = __fsub_rn(1.0f, s);
    }

    float f0 = visible_fs[v0];
    float f1 = visible_fs[v1];

    ovr_s[wid][v0] = -1;
    ovr_s[wid][v1] = -1;
    __syncwarp();

    // ---- output layout: [ out(B) | h_old_all(DEPTH,B,V,D) | h_sel_all(DEPTH,B,D) ] ----
    float* out_scalar = out;
    float* h_old      = out + BATCH;
    float* h_sel_out  = h_old + (size_t)DEPTH * BATCH * V * D;

    for (int i = 0; i < DEPTH; ++i) {
        const float li0 = Ls[i][v0];
        const float li1 = Ls[i][v1];
        const float r0 = __fdiv_rn(1.0f, __fadd_rn(li0, 1e-20f));
        const float r1 = __fdiv_rn(1.0f, __fadd_rn(li1, 1e-20f));

        // ---- seeds for argmin (wd = w * recip) and f-reduce; trees are pipelined below ----
        float wd0 = __fmul_rn(w0, r0);
        float wd1 = __fmul_rn(w1, r1);
        unsigned long long k0 = ((unsigned long long)float_to_ordered(wd0) << 32) | (unsigned)v0;
        unsigned long long k1 = ((unsigned long long)float_to_ordered(wd1) << 32) | (unsigned)v1;
        unsigned long long kk = k0 < k1 ? k0 : k1;
        float fp = __fmaf_rn(li0, f0, __fmul_rn(li1, f1));

        // ---- snapshot h_old + h_sel dot, with the two shuffle trees software-pipelined
        //      into the store stream (one stage per 8-iter chunk; stores never go silent) ----
        float acc0 = 0.0f, acc1 = 0.0f;
        float* dst = h_old + ((size_t)i * BATCH + b) * (V * D);
        int off = 16;
        #pragma unroll
        for (int c = 0; c < 8; ++c) {
            #pragma unroll
            for (int u = 0; u < 8; ++u) {
                const int v = c * 8 + u;
                const float liv = Ls[i][v];
                const int   j   = ovr_s[wid][v];
                const float* src = (j >= 0) ? &hsel_s[wid][j][0] : &vu_s[v][0];
                const float s0 = src[lane];
                const float s1 = src[32 + lane];
                acc0 = __fmaf_rn(liv, s0, acc0);
                acc1 = __fmaf_rn(liv, s1, acc1);
                __stcs(&dst[v * D + lane], s0);                     // d = lane (0..31)
                if (lane < 31) __stcs(&dst[v * D + 32 + lane], s1); // d = 32+lane (32..62)
            }
            if (c < 5) {   // 5 tree stages: o = 16,8,4,2,1 (same op order as before)
                unsigned long long other = __shfl_xor_sync(FULL, kk, off);
                kk = other < kk ? other : kk;
                fp = __fadd_rn(fp, __shfl_xor_sync(FULL, fp, off));
                off >>= 1;
            }
        }

        const int idx = (int)(unsigned)kk;
        unsigned ub = (unsigned)(kk >> 32);
        ub = (ub & 0x80000000u) ? (ub & 0x7fffffffu) : ~ub;
        const float val = __uint_as_float(ub);
        const float f_sel = __fadd_rn(fp, bias_s[i]);

        // ---- w update: single-rounded FMA (measured-correct form) ----
        w0 = __fmaf_rn(-val, li0, w0);
        w1 = __fmaf_rn(-val, li1, w1);
        if (v0 == idx) w0 = val;
        if (v1 == idx) w1 = val;

        // ---- emit h_sel_all[i][b][:] ----
        float* hso = h_sel_out + ((size_t)i * BATCH + b) * D;
        __stcs(&hso[lane], acc0);
        if (lane < 31) __stcs(&hso[32 + lane], acc1);

        // ---- state updates: h[idx] <- h_sel (as override), f[idx] <- f_sel ----
        hsel_s[wid][i][lane]      = acc0;
        hsel_s[wid][i][32 + lane] = acc1;   // slot 63 is a 0-propagating pad, never output
        if (v0 == idx) f0 = f_sel;
        if (v1 == idx) f1 = f_sel;
        if (lane == (idx & 31)) ovr_s[wid][idx] = i;
        __syncwarp();
    }

    // ---- out[b] = w . f (exact f32 fma tree) ----
    float p = __fmaf_rn(w0, f0, __fmul_rn(w1, f1));
    #pragma unroll
    for (int o = 16; o; o >>= 1) p = __fadd_rn(p, __shfl_xor_sync(FULL, p, o));
    if (lane == 0) out_scalar[b] = p;
}

extern "C" void kernel_launch(void* const* d_in, const int* in_sizes, int n_in,
                              void* d_out, int out_size) {
    const float* inp         = (const float*)d_in[0];
    const float* L           = (const float*)d_in[1];
    const float* visible_fs  = (const float*)d_in[2];
    const float* vis_units   = (const float*)d_in[3];
    const float* biases      = (const float*)d_in[4];
    float* out = (float*)d_out;

    dim3 grid(BATCH / WPB);
    dim3 block(WPB * 32);
    scn_kernel<<<grid, block>>>(inp, L, visible_fs, vis_units, biases, out);
}

// round 16
// speedup vs baseline: 1.1542x; 1.1437x over previous
#include <cuda_runtime.h>
#include <stdint.h>

// Problem constants (fixed by the reference)
#define BATCH 4096
#define V     64
#define D     63
#define DEPTH 16
#define WPB   4            // warps (batch rows) per block
#define FULL  0xffffffffu

__device__ __forceinline__ unsigned float_to_ordered(float f) {
    unsigned u = __float_as_uint(f);
    return (u & 0x80000000u) ? ~u : (u | 0x80000000u);
}

__global__ __launch_bounds__(WPB * 32)
void scn_kernel(const float* __restrict__ inp,
                const float* __restrict__ L,
                const float* __restrict__ visible_fs,
                const float* __restrict__ visible_units,
                const float* __restrict__ biases,
                float* __restrict__ out)
{
    __shared__ float vu_s[V][64];                 // visible_units, D padded to 64 (16 KB)
    __shared__ float Ls[DEPTH][V];                // L matrix (4 KB)
    __shared__ float hsel_s[WPB][DEPTH][64];      // per-warp stored h_sel vectors (16 KB)
    __shared__ int   ovr_s[WPB][V];               // per-warp: depth of latest override, or -1 (1 KB)
    __shared__ float bias_s[DEPTH];
    // ~37.3 KB -> 6 blocks/SM

    const int tid  = threadIdx.x;
    const int wid  = tid >> 5;
    const int lane = tid & 31;

    // ---- block-shared loads ----
    for (int k = tid; k < V * D; k += blockDim.x)
        vu_s[k / D][k % D] = visible_units[k];
    for (int k = tid; k < DEPTH * V; k += blockDim.x)
        Ls[k / V][k % V] = L[k];
    if (tid < DEPTH) bias_s[tid] = biases[tid];
    if (tid < V)     vu_s[tid][63] = 0.0f;        // pad column (never consumed as output)
    __syncthreads();

    const int b = blockIdx.x * WPB + wid;         // batch row for this warp

    const int v0 = lane;                           // this lane owns v = lane and v = 32+lane
    const int v1 = 32 + lane;

    // ---- init per-row state: w (barycentric weights), f ----
    const float* inp_row = inp + (size_t)b * D;
    float w0 = (v0 == 0) ? 0.0f : inp_row[v0 - 1];
    float w1 = inp_row[v1 - 1];                    // v1-1 in [31,62], valid

    // sum(inp) then w[0] = 1 - sum  (order shown irrelevant)
    {
        float s = __fadd_rn(w0, w1);
        #pragma unroll
        for (int o = 16; o; o >>= 1) s = __fadd_rn(s, __shfl_xor_sync(FULL, s, o));
        if (lane == 0) w0 = __fsub_rn(1.0f, s);
    }

    float f0 = visible_fs[v0];
    float f1 = visible_fs[v1];

    ovr_s[wid][v0] = -1;
    ovr_s[wid][v1] = -1;
    __syncwarp();

    // ---- output layout: [ out(B) | h_old_all(DEPTH,B,V,D) | h_sel_all(DEPTH,B,D) ] ----
    float* out_scalar = out;
    float* h_old      = out + BATCH;
    float* h_sel_out  = h_old + (size_t)DEPTH * BATCH * V * D;

    for (int i = 0; i < DEPTH; ++i) {
        const float li0 = Ls[i][v0];
        const float li1 = Ls[i][v1];
        // correctly-rounded reciprocal (XLA recip-mul rewrite), in-register
        const float r0 = __fdiv_rn(1.0f, __fadd_rn(li0, 1e-20f));
        const float r1 = __fdiv_rn(1.0f, __fadd_rn(li1, 1e-20f));

        // ---- argmin of wd = w * fl(1/(Li+1e-20))  [XLA recip-mul], first-index tie-break ----
        float wd0 = __fmul_rn(w0, r0);
        float wd1 = __fmul_rn(w1, r1);
        unsigned long long k0 = ((unsigned long long)float_to_ordered(wd0) << 32) | (unsigned)v0;
        unsigned long long k1 = ((unsigned long long)float_to_ordered(wd1) << 32) | (unsigned)v1;
        unsigned long long kk = k0 < k1 ? k0 : k1;
        #pragma unroll
        for (int o = 16; o; o >>= 1) {
            unsigned long long other = __shfl_xor_sync(FULL, kk, o);
            kk = other < kk ? other : kk;
        }
        const int idx = (int)(unsigned)kk;
        // recover min value exactly (inverse monotone map)
        unsigned ub = (unsigned)(kk >> 32);
        ub = (ub & 0x80000000u) ? (ub & 0x7fffffffu) : ~ub;
        const float val = __uint_as_float(ub);

        // ---- f_sel = Li . f + bias[i] ----
        float fp = __fmaf_rn(li0, f0, __fmul_rn(li1, f1));
        #pragma unroll
        for (int o = 16; o; o >>= 1) fp = __fadd_rn(fp, __shfl_xor_sync(FULL, fp, o));
        const float f_sel = __fadd_rn(fp, bias_s[i]);

        // ---- w update: single-rounded FMA (measured-correct form) ----
        w0 = __fmaf_rn(-val, li0, w0);
        w1 = __fmaf_rn(-val, li1, w1);
        if (v0 == idx) w0 = val;
        if (v1 == idx) w1 = val;

        // ---- snapshot h_old (pre-update) + h_sel = Li . h in same pass ----
        // streaming stores: data never re-read by this kernel
        float acc0 = 0.0f, acc1 = 0.0f;
        float* dst = h_old + ((size_t)i * BATCH + b) * (V * D);
        #pragma unroll 8
        for (int v = 0; v < V; ++v) {
            const float liv = Ls[i][v];
            const int   j   = ovr_s[wid][v];
            const float* src = (j >= 0) ? &hsel_s[wid][j][0] : &vu_s[v][0];
            const float s0 = src[lane];
            const float s1 = src[32 + lane];
            acc0 = __fmaf_rn(liv, s0, acc0);
            acc1 = __fmaf_rn(liv, s1, acc1);
            __stcs(&dst[v * D + lane], s0);                     // d = lane (0..31)
            if (lane < 31) __stcs(&dst[v * D + 32 + lane], s1); // d = 32+lane (32..62)
        }

        // ---- emit h_sel_all[i][b][:] ----
        float* hso = h_sel_out + ((size_t)i * BATCH + b) * D;
        __stcs(&hso[lane], acc0);
        if (lane < 31) __stcs(&hso[32 + lane], acc1);

        // ---- state updates: h[idx] <- h_sel (as override), f[idx] <- f_sel ----
        hsel_s[wid][i][lane]      = acc0;
        hsel_s[wid][i][32 + lane] = acc1;   // slot 63 is a 0-propagating pad, never output
        if (v0 == idx) f0 = f_sel;
        if (v1 == idx) f1 = f_sel;
        if (lane == (idx & 31)) ovr_s[wid][idx] = i;
        __syncwarp();
    }

    // ---- out[b] = w . f (exact f32 fma tree) ----
    float p = __fmaf_rn(w0, f0, __fmul_rn(w1, f1));
    #pragma unroll
    for (int o = 16; o; o >>= 1) p = __fadd_rn(p, __shfl_xor_sync(FULL, p, o));
    if (lane == 0) out_scalar[b] = p;
}

extern "C" void kernel_launch(void* const* d_in, const int* in_sizes, int n_in,
                              void* d_out, int out_size) {
    const float* inp         = (const float*)d_in[0];
    const float* L           = (const float*)d_in[1];
    const float* visible_fs  = (const float*)d_in[2];
    const float* vis_units   = (const float*)d_in[3];
    const float* biases      = (const float*)d_in[4];
    float* out = (float*)d_out;

    dim3 grid(BATCH / WPB);
    dim3 block(WPB * 32);
    scn_kernel<<<grid, block>>>(inp, L, visible_fs, vis_units, biases, out);
}